// round 12
// baseline (speedup 1.0000x reference)
#include <cuda_runtime.h>
#include <cstdint>
#include <math_constants.h>

#define BATCH 16
#define NPRED 1024
#define NGT   1024
#define NP1   1025
#define NCLS  3
#define M_BASE 3
#define SEG_A  32              // compute segs per sample
#define FILL_SEG 5             // fill segs per sample -> 80 fill blocks
#define TPB_A  512
#define NBKT   1056            // 33 ins-groups x 32 orders
#define SG_BASE (M_BASE + BATCH * NP1 * NP1)
#define M_END   (M_BASE + BATCH * NP1 * NP1)    // 16,810,003
#define FILL_THREADS (BATCH * FILL_SEG * TPB_A) // 40960

__device__ uint32_t g_keys[BATCH * NPRED];
__device__ float g_closs[BATCH * SEG_A];
__device__ float g_semloss[BATCH * SEG_A];
__device__ float g_mloss[BATCH];
__device__ int   g_done;    // self-resetting ticket

// Packed f32x2 ops (per-lane .rn — bit-identical to __fadd_rn/__fmul_rn)
#define ADDX2(o, a, b) asm("add.rn.f32x2 %0, %1, %2;" : "=l"(o) : "l"(a), "l"(b))
#define MULX2(o, a, b) asm("mul.rn.f32x2 %0, %1, %2;" : "=l"(o) : "l"(a), "l"(b))
#define PACKX2(o, lo, hi) asm("mov.b64 %0, {%1, %2};" : "=l"(o) : "f"(lo), "f"(hi))
#define UNPKX2(lo, hi, in) asm("mov.b64 {%0, %1}, %2;" : "=f"(lo), "=f"(hi) : "l"(in))

// ---------------------------------------------------------------------------
// K1: 592 blocks = exactly one wave (4 x 512thr per SM).
//   seg <  32 : compute (nearest-GT + keys + FULL SG rows + loss partials)
//   seg >= 32 : fill the M region with zeros (contiguous strided float4)
// ---------------------------------------------------------------------------
__global__ void __launch_bounds__(TPB_A, 4) kernelK1(
    const float* __restrict__ positions,
    const float* __restrict__ semantics,
    const float* __restrict__ gt_pts,
    const int*   __restrict__ gt_ins,
    const int*   __restrict__ gt_order,
    const int*   __restrict__ gt_type,
    float* __restrict__ out)
{
    const int b    = blockIdx.x;
    const int seg  = blockIdx.y;
    const int tid  = threadIdx.x;

    if (seg >= SEG_A) {
        // ---------------- fill block: zero M region ----------------
        // floats [M_BASE, M_END): head = out[3], aligned float4 body, 3-float tail
        const int fid = (seg - SEG_A) * BATCH + b;       // 0..79
        const int tl  = fid * TPB_A + tid;               // 0..40959
        const size_t s4 = 1;                             // float4 idx of element 4
        const size_t e4 = (size_t)M_END >> 2;            // 4,202,500
        float4* o4 = reinterpret_cast<float4*>(out);
        const float4 z = make_float4(0.f, 0.f, 0.f, 0.f);
        for (size_t i = s4 + tl; i < e4; i += FILL_THREADS) o4[i] = z;
        if (tl == 0) {
            out[3] = 0.f;                                // head
            out[(e4 << 2) + 0] = 0.f;                    // tail: 3 floats
            out[(e4 << 2) + 1] = 0.f;
            out[(e4 << 2) + 2] = 0.f;
        }
        return;
    }

    // ---------------- compute block (R11 A body) ----------------
    const int lane = tid & 31;
    const int w    = tid >> 5;

    __shared__ float4 npgt4[NGT / 2];           // 8 KB: (-x0,-y0,-x1,-y1)
    __shared__ float rc[16], rs[16];

    {   // npgt = -((gt + BOUND)/(2*BOUND)); BOUND = {30,15} exact in f32
        float4 g = reinterpret_cast<const float4*>(gt_pts + (size_t)b * NGT * 2)[tid];
        npgt4[tid] = make_float4(-__fdiv_rn(__fadd_rn(g.x, 30.0f), 60.0f),
                                 -__fdiv_rn(__fadd_rn(g.y, 15.0f), 30.0f),
                                 -__fdiv_rn(__fadd_rn(g.z, 30.0f), 60.0f),
                                 -__fdiv_rn(__fadd_rn(g.w, 15.0f), 30.0f));
    }
    __syncthreads();

    const int p0 = (seg * 16 + w) * 2;
    const int p1 = p0 + 1;
    const float2 q0 = reinterpret_cast<const float2*>(positions)[(size_t)b * NPRED + p0];
    const float2 q1 = reinterpret_cast<const float2*>(positions)[(size_t)b * NPRED + p1];
    const float px0 = __fdiv_rn(q0.x, 399.0f), py0 = __fdiv_rn(q0.y, 199.0f);
    const float px1 = __fdiv_rn(q1.x, 399.0f), py1 = __fdiv_rn(q1.y, 199.0f);

    unsigned long long P0, P1;
    PACKX2(P0, px0, py0);
    PACKX2(P1, px1, py1);

    float d0 = CUDART_INF_F, d1 = CUDART_INF_F;
    int   a0 = 2 * lane, a1 = 2 * lane;

    const ulonglong2* gsm = reinterpret_cast<const ulonglong2*>(npgt4);
    #pragma unroll
    for (int k = 0; k < 16; k++) {
        const int m = k * 32 + lane;
        const ulonglong2 G = gsm[m];            // LDS.128: 2 negated points
        const int j = 2 * m;
        unsigned long long s, q;
        float lo, hi, dd;
        ADDX2(s, P0, G.x); MULX2(q, s, s); UNPKX2(lo, hi, q);
        dd = __fadd_rn(lo, hi);
        if (dd < d0) { d0 = dd; a0 = j; }
        ADDX2(s, P1, G.x); MULX2(q, s, s); UNPKX2(lo, hi, q);
        dd = __fadd_rn(lo, hi);
        if (dd < d1) { d1 = dd; a1 = j; }
        ADDX2(s, P0, G.y); MULX2(q, s, s); UNPKX2(lo, hi, q);
        dd = __fadd_rn(lo, hi);
        if (dd < d0) { d0 = dd; a0 = j + 1; }
        ADDX2(s, P1, G.y); MULX2(q, s, s); UNPKX2(lo, hi, q);
        dd = __fadd_rn(lo, hi);
        if (dd < d1) { d1 = dd; a1 = j + 1; }
    }
    // warp reduce with first-occurrence tie-break (smaller index on ties)
    #pragma unroll
    for (int o = 16; o > 0; o >>= 1) {
        float od = __shfl_down_sync(0xFFFFFFFFu, d0, o);
        int   oa = __shfl_down_sync(0xFFFFFFFFu, a0, o);
        if (od < d0 || (od == d0 && oa < a0)) { d0 = od; a0 = oa; }
        od = __shfl_down_sync(0xFFFFFFFFu, d1, o);
        oa = __shfl_down_sync(0xFFFFFFFFu, a1, o);
        if (od < d1 || (od == d1 && oa < a1)) { d1 = od; a1 = oa; }
    }

    if (lane == 0) {
        const float t0 = 1.5f / 60.0f, t1 = 1.5f / 30.0f;
        const float thr = sqrtf(__fadd_rn(__fmul_rn(t0, t0), __fmul_rn(t1, t1)));
        float cl = 0.f, sl = 0.f;
        #pragma unroll
        for (int h = 0; h < 2; h++) {
            const int   p    = h ? p1 : p0;
            const float dmin = h ? d1 : d0;
            const int   amin = h ? a1 : a0;
            const float px   = h ? px1 : px0;
            const float py   = h ? py1 : py0;
            const bool valid = sqrtf(__fadd_rn(dmin, 1e-12f)) < thr;
            const int gi = gt_ins  [(size_t)b * NGT + amin];
            const int go = gt_order[(size_t)b * NGT + amin];
            const int gc = gt_type [(size_t)b * NGT + amin];
            g_keys[b * NPRED + p] = ((uint32_t)(valid ? (gi + 1) : 0) << 15) |
                                    ((uint32_t)go << 10) | (uint32_t)p;
            // write the FULL SG column (no memset coverage needed)
            float* sgp = out + SG_BASE + (size_t)b * NCLS * NPRED + p;
            sgp[0]         = (gc == 0) ? 1.0f : 0.0f;
            sgp[NPRED]     = (gc == 1) ? 1.0f : 0.0f;
            sgp[2 * NPRED] = (gc == 2) ? 1.0f : 0.0f;
            const float4 gq = npgt4[amin >> 1];      // negated coords
            const float ngx = (amin & 1) ? gq.z : gq.x;
            const float ngy = (amin & 1) ? gq.w : gq.y;
            cl += fabsf(__fadd_rn(px, ngx)) + fabsf(__fadd_rn(py, ngy));
            sl += semantics[(size_t)b * NCLS * NPRED + (size_t)gc * NPRED + p];
        }
        rc[w] = cl; rs[w] = sl;
    }
    __syncthreads();
    if (tid == 0) {
        float c = 0.f, s = 0.f;
        #pragma unroll
        for (int k = 0; k < 16; k++) { c += rc[k]; s += rs[k]; }
        g_closs  [b * SEG_A + seg] = c;
        g_semloss[b * SEG_A + seg] = s;
    }
}

// ---------------------------------------------------------------------------
// K2: counting sort + edges + M-ones + mloss gathers; last of 16 blocks
// writes the 3 scalars. grid 16 x 1024. (proven 11.4 us shape)
// ---------------------------------------------------------------------------
__global__ __launch_bounds__(1024) void kernelB(
    const float* __restrict__ matches,
    float* __restrict__ out)
{
    const int b    = blockIdx.x;
    const int tid  = threadIdx.x;
    const int lane = tid & 31;
    const int w    = tid >> 5;

    __shared__ unsigned char  hist[32 * NBKT];
    __shared__ uint32_t       srt[NPRED];
    __shared__ unsigned short cnt[NBKT];
    __shared__ unsigned short base[NBKT];
    __shared__ uint32_t       csum[33];
    __shared__ unsigned short tfs[NPRED], tbs[NPRED];
    __shared__ float red[32];
    __shared__ int sflag;

    const uint32_t key = g_keys[b * NPRED + tid];
    const uint32_t bkt = key >> 10;              // (ins+1)*32 + order, < 1056

    {   // zero histogram
        uint32_t* h4 = reinterpret_cast<uint32_t*>(hist);
        #pragma unroll
        for (int i = tid; i < (32 * NBKT) / 4; i += 1024) h4[i] = 0;
    }
    __syncthreads();

    // per-warp bucket counts + stable in-warp rank (lane order == idx order)
    const unsigned mmask  = __match_any_sync(0xFFFFFFFFu, bkt);
    const int      inwarp = __popc(mmask & ((1u << lane) - 1u));
    if ((int)(__ffs(mmask) - 1) == lane)
        hist[w * NBKT + bkt] = (unsigned char)__popc(mmask);
    __syncthreads();

    // per-bucket: exclusive prefix over 32 warp-chunks + bucket total
    for (int q = tid; q < NBKT; q += 1024) {
        int run = 0;
        #pragma unroll
        for (int w2 = 0; w2 < 32; w2++) {
            int c = hist[w2 * NBKT + q];
            hist[w2 * NBKT + q] = (unsigned char)run;
            run += c;
        }
        cnt[q] = (unsigned short)run;
    }
    __syncthreads();

    // exclusive scan of cnt[0..1055] -> base[]
    {
        int v = cnt[tid];
        int inc = v;
        #pragma unroll
        for (int o = 1; o < 32; o <<= 1) {
            int t = __shfl_up_sync(0xFFFFFFFFu, inc, o);
            if (lane >= o) inc += t;
        }
        base[tid] = (unsigned short)(inc - v);
        if (lane == 31) csum[w] = (uint32_t)inc;
    }
    __syncthreads();
    if (w == 0) {
        uint32_t v = csum[lane];
        uint32_t inc = v;
        #pragma unroll
        for (int o = 1; o < 32; o <<= 1) {
            uint32_t t = __shfl_up_sync(0xFFFFFFFFu, inc, o);
            if (lane >= o) inc += t;
        }
        csum[lane] = inc - v;
        if (lane == 31) csum[32] = inc;
    }
    __syncthreads();
    base[tid] = (unsigned short)(base[tid] + csum[w]);
    if (w == 0) {
        int v = cnt[1024 + lane];
        int inc = v;
        #pragma unroll
        for (int o = 1; o < 32; o <<= 1) {
            int t = __shfl_up_sync(0xFFFFFFFFu, inc, o);
            if (lane >= o) inc += t;
        }
        base[1024 + lane] = (unsigned short)(inc - v + csum[32]);
    }
    tfs[tid] = NPRED;
    tbs[tid] = NPRED;
    __syncthreads();

    // stable scatter: rank = bucket base + chunk prefix + in-warp rank
    {
        const int rank = (int)base[bkt] + (int)hist[w * NBKT + bkt] + inwarp;
        srt[rank] = key;
    }
    __syncthreads();

    // chain edges between consecutive sorted keys with same valid ins group
    if (tid < NPRED - 1) {
        uint32_t ka = srt[tid], kb = srt[tid + 1];
        uint32_t ga = ka >> 15;
        if (ga == (kb >> 15) && ga != 0) {
            tfs[ka & 1023] = (unsigned short)(kb & 1023);
            tbs[kb & 1023] = (unsigned short)(ka & 1023);
        }
    }
    __syncthreads();

    // ones scatter (zeros already laid by K1's fill blocks) + mloss gathers
    const int f  = tfs[tid];
    const int bk = tbs[tid];
    const size_t mslice = (size_t)b * NP1 * NP1;
    const size_t row    = mslice + (size_t)tid * NP1;

    out[M_BASE + row + f] = 1.0f;                // M[i][t_fwd]=1 (incl. col n)
    if (bk == NPRED)                             // M[n][i]=1 iff no incoming
        out[M_BASE + mslice + (size_t)NPRED * NP1 + tid] = 1.0f;

    float mv = matches[row + f] + matches[row + bk];
    #pragma unroll
    for (int o = 16; o > 0; o >>= 1)
        mv += __shfl_down_sync(0xFFFFFFFFu, mv, o);
    if (lane == 0) red[w] = mv;
    __syncthreads();

    if (tid == 0) {
        float m = 0.f;
        #pragma unroll
        for (int k = 0; k < 32; k++) m += red[k];
        g_mloss[b] = m;
        __threadfence();                         // tiny: one float + ticket
        int t = atomicAdd(&g_done, 1);
        sflag = (t == BATCH - 1);
    }
    __syncthreads();
    if (!sflag) return;

    // ---- winner: final 3 scalars (fixed order, deterministic) ----
    {
        float c = (tid < BATCH * SEG_A) ? __ldcg(&g_closs[tid])   : 0.f;
        float s = (tid < BATCH * SEG_A) ? __ldcg(&g_semloss[tid]) : 0.f;
        #pragma unroll
        for (int o = 16; o > 0; o >>= 1) {
            c += __shfl_down_sync(0xFFFFFFFFu, c, o);
            s += __shfl_down_sync(0xFFFFFFFFu, s, o);
        }
        __shared__ float rc2[32], rs2[32];
        if (lane == 0) { rc2[w] = c; rs2[w] = s; }
        __syncthreads();
        if (tid == 0) {
            float ct = 0.f, st = 0.f, mt = 0.f;
            #pragma unroll
            for (int k = 0; k < 32; k++) { ct += rc2[k]; st += rs2[k]; }
            #pragma unroll
            for (int k = 0; k < BATCH; k++) mt += __ldcg(&g_mloss[k]);
            out[0] =  ct / (float)(BATCH * NPRED * 2);
            out[1] = -mt / (float)(BATCH * NPRED);
            out[2] = -st / (float)(BATCH * NPRED);
            g_done = 0;                          // reset for next graph replay
        }
    }
}

extern "C" void kernel_launch(void* const* d_in, const int* in_sizes, int n_in,
                              void* d_out, int out_size)
{
    const float* matches   = (const float*)d_in[0];
    const float* positions = (const float*)d_in[1];
    const float* semantics = (const float*)d_in[2];
    // d_in[3] = masks (all ones, unused)
    const float* gt_pts    = (const float*)d_in[4];
    const int*   gt_ins    = (const int*)  d_in[5];
    const int*   gt_order  = (const int*)  d_in[6];
    const int*   gt_type   = (const int*)  d_in[7];
    float* out = (float*)d_out;

    kernelK1<<<dim3(BATCH, SEG_A + FILL_SEG), TPB_A>>>(positions, semantics,
                                                       gt_pts, gt_ins, gt_order,
                                                       gt_type, out);
    kernelB<<<BATCH, 1024>>>(matches, out);
}

// round 13
// speedup vs baseline: 1.0977x; 1.0977x over previous
#include <cuda_runtime.h>
#include <cstdint>
#include <math_constants.h>

#define BATCH 16
#define NPRED 1024
#define NGT   1024
#define NP1   1025
#define NCLS  3
#define M_BASE 3
#define M_COUNT (BATCH * NP1 * NP1)
#define SEG_A  32
#define TPB_A  512
#define SG_BASE (M_BASE + M_COUNT)

__device__ uint32_t g_keys[BATCH * NPRED];
__device__ float g_closs[BATCH * SEG_A];
__device__ float g_semloss[BATCH * SEG_A];
__device__ float g_mloss[BATCH];
__device__ int   g_done;    // self-resetting ticket

// Packed f32x2 ops (per-lane .rn — bit-identical to __fadd_rn/__fmul_rn)
#define ADDX2(o, a, b) asm("add.rn.f32x2 %0, %1, %2;" : "=l"(o) : "l"(a), "l"(b))
#define MULX2(o, a, b) asm("mul.rn.f32x2 %0, %1, %2;" : "=l"(o) : "l"(a), "l"(b))
#define PACKX2(o, lo, hi) asm("mov.b64 %0, {%1, %2};" : "=l"(o) : "f"(lo), "f"(hi))
#define UNPKX2(lo, hi, in) asm("mov.b64 {%0, %1}, %2;" : "=f"(lo), "=f"(hi) : "l"(in))

// ---------------------------------------------------------------------------
// A: nearest-GT + keys + FULL SG rows + closs/semloss partials.
// grid (16, 32) x 512. Runs CONCURRENTLY with the M-region memset (disjoint).
// ---------------------------------------------------------------------------
__global__ __launch_bounds__(TPB_A) void kernelA(
    const float* __restrict__ positions,
    const float* __restrict__ semantics,
    const float* __restrict__ gt_pts,
    const int*   __restrict__ gt_ins,
    const int*   __restrict__ gt_order,
    const int*   __restrict__ gt_type,
    float* __restrict__ out)
{
    const int b    = blockIdx.x;
    const int seg  = blockIdx.y;
    const int tid  = threadIdx.x;
    const int lane = tid & 31;
    const int w    = tid >> 5;

    __shared__ float4 npgt4[NGT / 2];           // 8 KB: (-x0,-y0,-x1,-y1)
    __shared__ float rc[16], rs[16];

    {   // npgt = -((gt + BOUND)/(2*BOUND)); BOUND = {30,15} exact in f32
        float4 g = reinterpret_cast<const float4*>(gt_pts + (size_t)b * NGT * 2)[tid];
        npgt4[tid] = make_float4(-__fdiv_rn(__fadd_rn(g.x, 30.0f), 60.0f),
                                 -__fdiv_rn(__fadd_rn(g.y, 15.0f), 30.0f),
                                 -__fdiv_rn(__fadd_rn(g.z, 30.0f), 60.0f),
                                 -__fdiv_rn(__fadd_rn(g.w, 15.0f), 30.0f));
    }
    __syncthreads();

    const int p0 = (seg * 16 + w) * 2;
    const int p1 = p0 + 1;
    const float2 q0 = reinterpret_cast<const float2*>(positions)[(size_t)b * NPRED + p0];
    const float2 q1 = reinterpret_cast<const float2*>(positions)[(size_t)b * NPRED + p1];
    const float px0 = __fdiv_rn(q0.x, 399.0f), py0 = __fdiv_rn(q0.y, 199.0f);
    const float px1 = __fdiv_rn(q1.x, 399.0f), py1 = __fdiv_rn(q1.y, 199.0f);

    unsigned long long P0, P1;
    PACKX2(P0, px0, py0);
    PACKX2(P1, px1, py1);

    float d0 = CUDART_INF_F, d1 = CUDART_INF_F;
    int   a0 = 2 * lane, a1 = 2 * lane;

    const ulonglong2* gsm = reinterpret_cast<const ulonglong2*>(npgt4);
    #pragma unroll
    for (int k = 0; k < 16; k++) {
        const int m = k * 32 + lane;
        const ulonglong2 G = gsm[m];            // LDS.128: 2 negated points
        const int j = 2 * m;
        unsigned long long s, q;
        float lo, hi, dd;
        ADDX2(s, P0, G.x); MULX2(q, s, s); UNPKX2(lo, hi, q);
        dd = __fadd_rn(lo, hi);
        if (dd < d0) { d0 = dd; a0 = j; }
        ADDX2(s, P1, G.x); MULX2(q, s, s); UNPKX2(lo, hi, q);
        dd = __fadd_rn(lo, hi);
        if (dd < d1) { d1 = dd; a1 = j; }
        ADDX2(s, P0, G.y); MULX2(q, s, s); UNPKX2(lo, hi, q);
        dd = __fadd_rn(lo, hi);
        if (dd < d0) { d0 = dd; a0 = j + 1; }
        ADDX2(s, P1, G.y); MULX2(q, s, s); UNPKX2(lo, hi, q);
        dd = __fadd_rn(lo, hi);
        if (dd < d1) { d1 = dd; a1 = j + 1; }
    }
    // warp reduce with first-occurrence tie-break (smaller index on ties)
    #pragma unroll
    for (int o = 16; o > 0; o >>= 1) {
        float od = __shfl_down_sync(0xFFFFFFFFu, d0, o);
        int   oa = __shfl_down_sync(0xFFFFFFFFu, a0, o);
        if (od < d0 || (od == d0 && oa < a0)) { d0 = od; a0 = oa; }
        od = __shfl_down_sync(0xFFFFFFFFu, d1, o);
        oa = __shfl_down_sync(0xFFFFFFFFu, a1, o);
        if (od < d1 || (od == d1 && oa < a1)) { d1 = od; a1 = oa; }
    }

    if (lane == 0) {
        const float t0 = 1.5f / 60.0f, t1 = 1.5f / 30.0f;
        const float thr = sqrtf(__fadd_rn(__fmul_rn(t0, t0), __fmul_rn(t1, t1)));
        float cl = 0.f, sl = 0.f;
        #pragma unroll
        for (int h = 0; h < 2; h++) {
            const int   p    = h ? p1 : p0;
            const float dmin = h ? d1 : d0;
            const int   amin = h ? a1 : a0;
            const float px   = h ? px1 : px0;
            const float py   = h ? py1 : py0;
            const bool valid = sqrtf(__fadd_rn(dmin, 1e-12f)) < thr;
            const int gi = gt_ins  [(size_t)b * NGT + amin];
            const int go = gt_order[(size_t)b * NGT + amin];
            const int gc = gt_type [(size_t)b * NGT + amin];
            g_keys[b * NPRED + p] = ((uint32_t)(valid ? (gi + 1) : 0) << 15) |
                                    ((uint32_t)go << 10) | (uint32_t)p;
            // FULL SG column (memset does NOT cover SG — avoids the race)
            float* sgp = out + SG_BASE + (size_t)b * NCLS * NPRED + p;
            sgp[0]         = (gc == 0) ? 1.0f : 0.0f;
            sgp[NPRED]     = (gc == 1) ? 1.0f : 0.0f;
            sgp[2 * NPRED] = (gc == 2) ? 1.0f : 0.0f;
            const float4 gq = npgt4[amin >> 1];      // negated coords
            const float ngx = (amin & 1) ? gq.z : gq.x;
            const float ngy = (amin & 1) ? gq.w : gq.y;
            cl += fabsf(__fadd_rn(px, ngx)) + fabsf(__fadd_rn(py, ngy));
            sl += semantics[(size_t)b * NCLS * NPRED + (size_t)gc * NPRED + p];
        }
        rc[w] = cl; rs[w] = sl;
    }
    __syncthreads();
    if (tid == 0) {
        float c = 0.f, s = 0.f;
        #pragma unroll
        for (int k = 0; k < 16; k++) { c += rc[k]; s += rs[k]; }
        g_closs  [b * SEG_A + seg] = c;
        g_semloss[b * SEG_A + seg] = s;
    }
}

// ---------------------------------------------------------------------------
// B: register+shuffle bitonic sort (proven 10.9 us shape) + edges + M-ones +
// mloss gathers; last of 16 blocks writes the 3 scalars. grid 16 x 1024.
// ---------------------------------------------------------------------------
__global__ __launch_bounds__(1024) void kernelB(
    const float* __restrict__ matches,
    float* __restrict__ out)
{
    const int b = blockIdx.x;
    const int i = threadIdx.x;
    const int lane = i & 31, w = i >> 5;

    __shared__ uint32_t buf[2][NPRED];
    __shared__ unsigned short tf[NPRED], tb[NPRED];
    __shared__ float red[32];
    __shared__ int sflag;

    uint32_t v = g_keys[b * NPRED + i];
    tf[i] = NPRED;
    tb[i] = NPRED;

    int cur = 0;
    for (unsigned k = 2; k <= NPRED; k <<= 1) {
        const bool asc = ((i & k) == 0);
        for (unsigned j = k >> 1; j > 0; j >>= 1) {
            uint32_t pv;
            if (j >= 32) {
                buf[cur][i] = v;
                __syncthreads();
                pv = buf[cur][i ^ j];
                cur ^= 1;
            } else {
                pv = __shfl_xor_sync(0xFFFFFFFFu, v, j);
            }
            const bool lower = ((i & j) == 0);
            uint32_t mn = v < pv ? v : pv;
            uint32_t mx = v < pv ? pv : v;
            v = (lower == asc) ? mn : mx;
        }
    }

    buf[cur][i] = v;
    __syncthreads();

    // chain edges between consecutive sorted keys with same valid ins group
    if (i < NPRED - 1) {
        uint32_t ka = buf[cur][i], kb = buf[cur][i + 1];
        uint32_t ga = ka >> 15;
        if (ga == (kb >> 15) && ga != 0) {
            tf[ka & 1023] = (unsigned short)(kb & 1023);
            tb[kb & 1023] = (unsigned short)(ka & 1023);
        }
    }
    __syncthreads();

    // ones scatter (zeros laid by the parallel memset) + mloss gathers
    const int f  = tf[i];
    const int bk = tb[i];
    const size_t mslice = (size_t)b * NP1 * NP1;
    const size_t row    = mslice + (size_t)i * NP1;

    out[M_BASE + row + f] = 1.0f;                // M[i][t_fwd]=1 (incl. col n)
    if (bk == NPRED)                             // M[n][i]=1 iff no incoming
        out[M_BASE + mslice + (size_t)NPRED * NP1 + i] = 1.0f;

    float mv = matches[row + f] + matches[row + bk];
    #pragma unroll
    for (int o = 16; o > 0; o >>= 1)
        mv += __shfl_down_sync(0xFFFFFFFFu, mv, o);
    if (lane == 0) red[w] = mv;
    __syncthreads();

    if (i == 0) {
        float m = 0.f;
        #pragma unroll
        for (int k = 0; k < 32; k++) m += red[k];
        g_mloss[b] = m;
        __threadfence();                         // tiny: one float + ticket
        int t = atomicAdd(&g_done, 1);
        sflag = (t == BATCH - 1);
    }
    __syncthreads();
    if (!sflag) return;

    // ---- winner: final 3 scalars (fixed order, deterministic) ----
    {
        float c = (i < BATCH * SEG_A) ? __ldcg(&g_closs[i])   : 0.f;
        float s = (i < BATCH * SEG_A) ? __ldcg(&g_semloss[i]) : 0.f;
        #pragma unroll
        for (int o = 16; o > 0; o >>= 1) {
            c += __shfl_down_sync(0xFFFFFFFFu, c, o);
            s += __shfl_down_sync(0xFFFFFFFFu, s, o);
        }
        __shared__ float rc2[32], rs2[32];
        if (lane == 0) { rc2[w] = c; rs2[w] = s; }
        __syncthreads();
        if (i == 0) {
            float ct = 0.f, st = 0.f, mt = 0.f;
            #pragma unroll
            for (int k = 0; k < 32; k++) { ct += rc2[k]; st += rs2[k]; }
            #pragma unroll
            for (int k = 0; k < BATCH; k++) mt += __ldcg(&g_mloss[k]);
            out[0] =  ct / (float)(BATCH * NPRED * 2);
            out[1] = -mt / (float)(BATCH * NPRED);
            out[2] = -st / (float)(BATCH * NPRED);
            g_done = 0;                          // reset for next replay
        }
    }
}

extern "C" void kernel_launch(void* const* d_in, const int* in_sizes, int n_in,
                              void* d_out, int out_size)
{
    const float* matches   = (const float*)d_in[0];
    const float* positions = (const float*)d_in[1];
    const float* semantics = (const float*)d_in[2];
    // d_in[3] = masks (all ones, unused)
    const float* gt_pts    = (const float*)d_in[4];
    const int*   gt_ins    = (const int*)  d_in[5];
    const int*   gt_order  = (const int*)  d_in[6];
    const int*   gt_type   = (const int*)  d_in[7];
    float* out = (float*)d_out;

    // Lazily created resource handles (identical, deterministic work per call;
    // no device-memory allocation happens here).
    static cudaStream_t s2 = nullptr;
    static cudaEvent_t evFork = nullptr, evJoin = nullptr;
    if (s2 == nullptr) {
        cudaStreamCreateWithFlags(&s2, cudaStreamNonBlocking);
        cudaEventCreateWithFlags(&evFork, cudaEventDisableTiming);
        cudaEventCreateWithFlags(&evJoin, cudaEventDisableTiming);
    }

    // Fork: memset of the M region runs in parallel with kernelA
    // (disjoint ranges: memset covers [3, 3+M_COUNT); A writes SG + scalars' none).
    cudaEventRecord(evFork, 0);
    cudaStreamWaitEvent(s2, evFork, 0);
    cudaMemsetAsync(out + M_BASE, 0, (size_t)M_COUNT * sizeof(float), s2);
    cudaEventRecord(evJoin, s2);

    kernelA<<<dim3(BATCH, SEG_A), TPB_A>>>(positions, semantics, gt_pts,
                                           gt_ins, gt_order, gt_type, out);

    // Join: B needs both the zeros (memset) and the keys (A)
    cudaStreamWaitEvent(0, evJoin, 0);
    kernelB<<<BATCH, 1024>>>(matches, out);
}